// round 5
// baseline (speedup 1.0000x reference)
#include <cuda_runtime.h>

#define H  2048
#define SW 256
#define SD 200
#define O  128
#define IH (H + SW)   // 2304

#define NB_PROL 259
#define NB_GRU  2048
#define NB_STK  50      // 4 depth rows per block
#define NB_DEC  128
#define NB_TOT  (NB_PROL + NB_GRU + NB_STK + NB_DEC)  // 2485

// ---- scratch (device globals; zero-initialized at module load) ----
__device__ float g_logits[3];
__device__ float g_sin[SW];
__device__ float g_hnew[H];
__device__ int   g_prol_cnt;
__device__ int   g_done;
__device__ int   g_exit;

__device__ __forceinline__ float dot4(float4 a, float4 b) {
    return a.x*b.x + a.y*b.y + a.z*b.z + a.w*b.w;
}

__device__ __forceinline__ void softmax3(float& pp, float& po, float& pn) {
    float l0 = __ldcg(&g_logits[0]);
    float l1 = __ldcg(&g_logits[1]);
    float l2 = __ldcg(&g_logits[2]);
    float m  = fmaxf(l0, fmaxf(l1, l2));
    float e0 = __expf(l0 - m), e1 = __expf(l1 - m), e2 = __expf(l2 - m);
    float inv = 1.0f / (e0 + e1 + e2);
    pp = e0 * inv; po = e1 * inv; pn = e2 * inv;
}

__device__ __forceinline__ void block_exit_reset() {
    // thread 0 only. Orders prior atomics/stores before the exit-add.
    __threadfence();
    int old = atomicAdd(&g_exit, 1);
    if (old == NB_TOT - 1) {
        atomicExch(&g_prol_cnt, 0);
        atomicExch(&g_done, 0);
        __threadfence();
        atomicExch(&g_exit, 0);
    }
}

__global__ void __launch_bounds__(256) fused_kernel(
    const float* __restrict__ hidden,
    const int*   __restrict__ inp,
    const float* __restrict__ emb,
    const float* __restrict__ Wc, const float* __restrict__ bc,
    const float* __restrict__ Ws, const float* __restrict__ bs,
    const float* __restrict__ W_ih, const float* __restrict__ b_ih,
    const float* __restrict__ W_hh, const float* __restrict__ b_hh,
    const float* __restrict__ Wd, const float* __restrict__ bd,
    const float* __restrict__ stack,
    float* __restrict__ out_o, float* __restrict__ out_h,
    float* __restrict__ out_stack)
{
    int b = blockIdx.x;
    int t = threadIdx.x;
    int lane = t & 31, wid = t >> 5;
    const float4* h4 = reinterpret_cast<const float4*>(hidden);

    if (b < NB_PROL) {
        // ================= prologue: one dot of length H =================
        int r = b;
        const float* rowp = (r < 3) ? (Wc + (size_t)r * H)
                                    : (Ws + (size_t)(r - 3) * H);
        const float4* w4 = reinterpret_cast<const float4*>(rowp);
        float4 a0 = w4[t], a1 = w4[t + 256];
        float4 h0 = h4[t], h1 = h4[t + 256];
        float s = dot4(a0, h0) + dot4(a1, h1);
        __shared__ float sm[8];
        #pragma unroll
        for (int o = 16; o > 0; o >>= 1) s += __shfl_down_sync(0xffffffffu, s, o);
        if (lane == 0) sm[wid] = s;
        __syncthreads();
        if (t == 0) {
            float S = 0.f;
            #pragma unroll
            for (int j = 0; j < 8; j++) S += sm[j];
            if (r < 3) g_logits[r] = S + bc[r];
            else       g_sin[r - 3] = tanhf(S + bs[r - 3]);
            __threadfence();
            atomicAdd(&g_prol_cnt, 1);
            block_exit_reset();
        }
        return;
    }

    if (b < NB_PROL + NB_GRU) {
        // ================= GRU row i =================
        int i = b - NB_PROL;
        const float* x = emb + (size_t)inp[0] * H;
        const float4* x4 = reinterpret_cast<const float4*>(x);
        const float4* wi_r = reinterpret_cast<const float4*>(W_ih + (size_t)i * IH);
        const float4* wi_z = reinterpret_cast<const float4*>(W_ih + (size_t)(H + i) * IH);
        const float4* wi_n = reinterpret_cast<const float4*>(W_ih + (size_t)(2 * H + i) * IH);
        const float4* wh_r = reinterpret_cast<const float4*>(W_hh + (size_t)i * H);
        const float4* wh_z = reinterpret_cast<const float4*>(W_hh + (size_t)(H + i) * H);
        const float4* wh_n = reinterpret_cast<const float4*>(W_hh + (size_t)(2 * H + i) * H);

        // ---- phase A: 6 dots over H (no dependencies) ----
        float acc_r = 0.f, acc_z = 0.f, gin = 0.f, ghn = 0.f;
        #pragma unroll
        for (int u = 0; u < 2; u++) {
            int k = t + u * 256;
            float4 xv = x4[k];
            float4 hv = h4[k];
            float4 a;
            a = wi_r[k]; acc_r += dot4(a, xv);
            a = wh_r[k]; acc_r += dot4(a, hv);
            a = wi_z[k]; acc_z += dot4(a, xv);
            a = wh_z[k]; acc_z += dot4(a, hv);
            a = wi_n[k]; gin   += dot4(a, xv);
            a = wh_n[k]; ghn   += dot4(a, hv);
        }

        // ---- wait for prologue ----
        if (t == 0) {
            while (atomicAdd(&g_prol_cnt, 0) < NB_PROL) __nanosleep(32);
        }
        __syncthreads();

        // ---- phase B: stack_top columns (threads 0..63) ----
        if (t < SW / 4) {
            float pp, po, pn; softmax3(pp, po, pn);
            float4 v0 = __ldcg(reinterpret_cast<const float4*>(stack) + t);
            float4 v1 = __ldcg(reinterpret_cast<const float4*>(stack + SW) + t);
            float4 vs = __ldcg(reinterpret_cast<const float4*>(g_sin) + t);
            float4 st;
            st.x = pn*v0.x + pp*vs.x + po*v1.x;
            st.y = pn*v0.y + pp*vs.y + po*v1.y;
            st.z = pn*v0.z + pp*vs.z + po*v1.z;
            st.w = pn*v0.w + pp*vs.w + po*v1.w;
            int c = H / 4 + t;
            acc_r += dot4(wi_r[c], st);
            acc_z += dot4(wi_z[c], st);
            gin   += dot4(wi_n[c], st);
        }

        // ---- reduce 4 values across 8 warps ----
        __shared__ float sm[8][4];
        #pragma unroll
        for (int o = 16; o > 0; o >>= 1) {
            acc_r += __shfl_down_sync(0xffffffffu, acc_r, o);
            acc_z += __shfl_down_sync(0xffffffffu, acc_z, o);
            gin   += __shfl_down_sync(0xffffffffu, gin,   o);
            ghn   += __shfl_down_sync(0xffffffffu, ghn,   o);
        }
        if (lane == 0) { sm[wid][0]=acc_r; sm[wid][1]=acc_z; sm[wid][2]=gin; sm[wid][3]=ghn; }
        __syncthreads();
        if (t == 0) {
            float R = 0, Z = 0, GIN = 0, GHN = 0;
            #pragma unroll
            for (int j = 0; j < 8; j++) {
                R += sm[j][0]; Z += sm[j][1]; GIN += sm[j][2]; GHN += sm[j][3];
            }
            float r = 1.0f / (1.0f + expf(-(R + b_ih[i] + b_hh[i])));
            float z = 1.0f / (1.0f + expf(-(Z + b_ih[H + i] + b_hh[H + i])));
            float n = tanhf(GIN + b_ih[2 * H + i] + r * (GHN + b_hh[2 * H + i]));
            float hn = (1.0f - z) * n + z * hidden[i];
            out_h[i]  = hn;
            g_hnew[i] = hn;
            __threadfence();
            atomicAdd(&g_done, 1);
            block_exit_reset();
        }
        return;
    }

    if (b < NB_PROL + NB_GRU + NB_STK) {
        // ================= stack update: 4 depth rows per block =================
        int d = 4 * (b - NB_PROL - NB_GRU) + (t >> 6);
        int c = t & 63;
        if (t == 0) {
            while (atomicAdd(&g_prol_cnt, 0) < NB_PROL) __nanosleep(32);
        }
        __syncthreads();
        float pp, po, pn; softmax3(pp, po, pn);
        float4 cur = reinterpret_cast<const float4*>(stack + (size_t)d * SW)[c];
        float4 down = make_float4(0.f, 0.f, 0.f, 0.f);
        if (d < SD - 1)
            down = reinterpret_cast<const float4*>(stack + (size_t)(d + 1) * SW)[c];
        float4 up = (d == 0)
            ? __ldcg(reinterpret_cast<const float4*>(g_sin) + c)
            : reinterpret_cast<const float4*>(stack + (size_t)(d - 1) * SW)[c];
        float4 o;
        o.x = pn*cur.x + pp*up.x + po*down.x;
        o.y = pn*cur.y + pp*up.y + po*down.y;
        o.z = pn*cur.z + pp*up.z + po*down.z;
        o.w = pn*cur.w + pp*up.w + po*down.w;
        reinterpret_cast<float4*>(out_stack)[(size_t)d * (SW / 4) + c] = o;
        __syncthreads();
        if (t == 0) block_exit_reset();
        return;
    }

    // ================= decoder row =================
    {
        int row = b - NB_PROL - NB_GRU - NB_STK;
        if (t == 0) {
            while (atomicAdd(&g_done, 0) < NB_GRU) __nanosleep(32);
        }
        __syncthreads();
        const float4* w4 = reinterpret_cast<const float4*>(Wd + (size_t)row * H);
        const float4* hn4 = reinterpret_cast<const float4*>(g_hnew);
        float4 a0 = w4[t], a1 = w4[t + 256];
        float4 v0 = __ldcg(hn4 + t), v1 = __ldcg(hn4 + t + 256);
        float s = dot4(a0, v0) + dot4(a1, v1);
        __shared__ float sm[8];
        #pragma unroll
        for (int o = 16; o > 0; o >>= 1) s += __shfl_down_sync(0xffffffffu, s, o);
        if (lane == 0) sm[wid] = s;
        __syncthreads();
        if (t == 0) {
            float S = 0.f;
            #pragma unroll
            for (int j = 0; j < 8; j++) S += sm[j];
            out_o[row] = S + bd[row];
            block_exit_reset();
        }
    }
}

extern "C" void kernel_launch(void* const* d_in, const int* in_sizes, int n_in,
                              void* d_out, int out_size) {
    const int*   inp    = (const int*)  d_in[0];
    const float* hidden = (const float*)d_in[1];
    const float* stack  = (const float*)d_in[2];
    const float* emb    = (const float*)d_in[3];
    const float* Wc     = (const float*)d_in[4];
    const float* bc     = (const float*)d_in[5];
    const float* Ws     = (const float*)d_in[6];
    const float* bs     = (const float*)d_in[7];
    const float* W_ih   = (const float*)d_in[8];
    const float* b_ih   = (const float*)d_in[9];
    const float* W_hh   = (const float*)d_in[10];
    const float* b_hh   = (const float*)d_in[11];
    const float* Wd     = (const float*)d_in[12];
    const float* bd     = (const float*)d_in[13];

    float* out       = (float*)d_out;
    float* out_o     = out;            // (1,O)     : 128
    float* out_h     = out + O;        // (1,1,H)   : 2048
    float* out_stack = out + O + H;    // (1,SD,SW) : 51200

    fused_kernel<<<NB_TOT, 256>>>(hidden, inp, emb, Wc, bc, Ws, bs,
                                  W_ih, b_ih, W_hh, b_hh, Wd, bd, stack,
                                  out_o, out_h, out_stack);
}

// round 6
// speedup vs baseline: 1.0549x; 1.0549x over previous
#include <cuda_runtime.h>

#define H  2048
#define SW 256
#define SD 200
#define O  128
#define IH (H + SW)   // 2304

// ---- scratch (device globals) ----
__device__ float g_logits[3];
__device__ float g_sin[SW];
__device__ float g_pr[H];    // Wih_r[:H]·x + Whh_r·h
__device__ float g_pz[H];
__device__ float g_pgin[H];  // Wih_n[:H]·x
__device__ float g_pghn[H];  // Whh_n·h
__device__ float g_hnew[H];
__device__ int   g_done;

__device__ __forceinline__ float dot4(float4 a, float4 b) {
    return a.x*b.x + a.y*b.y + a.z*b.z + a.w*b.w;
}

// plain cached loads — g_logits written by K1 (kernel boundary, L1 flushed
// at launch) so L1 serves the broadcast after first touch per SM.
__device__ __forceinline__ void softmax3_cached(float& pp, float& po, float& pn) {
    float l0 = g_logits[0], l1 = g_logits[1], l2 = g_logits[2];
    float m  = fmaxf(l0, fmaxf(l1, l2));
    float e0 = __expf(l0 - m), e1 = __expf(l1 - m), e2 = __expf(l2 - m);
    float inv = 1.0f / (e0 + e1 + e2);
    pp = e0 * inv; po = e1 * inv; pn = e2 * inv;
}

// =====================================================================
// K1: blocks [0,2048): GRU main dots (partials). blocks [2048,2307):
// prologue dots (3 ctrl + 256 s_in). 256 threads.  (unchanged from R4,
// measured ~6 TB/s)
// =====================================================================
__global__ void __launch_bounds__(256) k1_kernel(
    const float* __restrict__ hidden,
    const int*   __restrict__ inp,
    const float* __restrict__ emb,
    const float* __restrict__ W_ih,
    const float* __restrict__ W_hh,
    const float* __restrict__ Wc, const float* __restrict__ bc,
    const float* __restrict__ Ws, const float* __restrict__ bs)
{
    int b = blockIdx.x;
    int t = threadIdx.x;
    const float4* h4 = reinterpret_cast<const float4*>(hidden);
    __shared__ float sm[8][4];
    int lane = t & 31, wid = t >> 5;

    if (b >= 2048) {
        int r = b - 2048;
        const float* rowp = (r < 3) ? (Wc + (size_t)r * H)
                                    : (Ws + (size_t)(r - 3) * H);
        const float4* w4 = reinterpret_cast<const float4*>(rowp);
        float4 a0 = w4[t], a1 = w4[t + 256];
        float4 h0 = h4[t], h1 = h4[t + 256];
        float s = dot4(a0, h0) + dot4(a1, h1);
        #pragma unroll
        for (int o = 16; o > 0; o >>= 1) s += __shfl_down_sync(0xffffffffu, s, o);
        if (lane == 0) sm[wid][0] = s;
        __syncthreads();
        if (t == 0) {
            float S = 0.f;
            #pragma unroll
            for (int j = 0; j < 8; j++) S += sm[j][0];
            if (r < 3) g_logits[r] = S + bc[r];
            else       g_sin[r - 3] = tanhf(S + bs[r - 3]);
            if (r == 0) g_done = 0;   // reset spin counter for K2
        }
        return;
    }

    int i = b;
    const float* x = emb + (size_t)inp[0] * H;
    const float4* x4 = reinterpret_cast<const float4*>(x);
    const float4* wi_r = reinterpret_cast<const float4*>(W_ih + (size_t)i * IH);
    const float4* wi_z = reinterpret_cast<const float4*>(W_ih + (size_t)(H + i) * IH);
    const float4* wi_n = reinterpret_cast<const float4*>(W_ih + (size_t)(2 * H + i) * IH);
    const float4* wh_r = reinterpret_cast<const float4*>(W_hh + (size_t)i * H);
    const float4* wh_z = reinterpret_cast<const float4*>(W_hh + (size_t)(H + i) * H);
    const float4* wh_n = reinterpret_cast<const float4*>(W_hh + (size_t)(2 * H + i) * H);

    float pr = 0.f, pz = 0.f, pgin = 0.f, pghn = 0.f;
    #pragma unroll
    for (int u = 0; u < 2; u++) {
        int k = t + u * 256;
        float4 xv = x4[k];
        float4 hv = h4[k];
        float4 a;
        a = wi_r[k]; pr   += dot4(a, xv);
        a = wh_r[k]; pr   += dot4(a, hv);
        a = wi_z[k]; pz   += dot4(a, xv);
        a = wh_z[k]; pz   += dot4(a, hv);
        a = wi_n[k]; pgin += dot4(a, xv);
        a = wh_n[k]; pghn += dot4(a, hv);
    }

    #pragma unroll
    for (int o = 16; o > 0; o >>= 1) {
        pr   += __shfl_down_sync(0xffffffffu, pr,   o);
        pz   += __shfl_down_sync(0xffffffffu, pz,   o);
        pgin += __shfl_down_sync(0xffffffffu, pgin, o);
        pghn += __shfl_down_sync(0xffffffffu, pghn, o);
    }
    if (lane == 0) { sm[wid][0]=pr; sm[wid][1]=pz; sm[wid][2]=pgin; sm[wid][3]=pghn; }
    __syncthreads();
    if (t < 4) {
        float v = 0.f;
        #pragma unroll
        for (int j = 0; j < 8; j++) v += sm[j][t];
        if      (t == 0) g_pr[i]   = v;
        else if (t == 1) g_pz[i]   = v;
        else if (t == 2) g_pgin[i] = v;
        else             g_pghn[i] = v;
    }
}

// =====================================================================
// K2: 64-thread blocks, all co-resident.
//   blocks [0,2048):    GRU finish — ALL pre-kernel data via plain
//                       cached loads (no .cg ⇒ no LTS line serialization)
//   blocks [2048,2248): stack update
//   blocks [2248,2376): decoder rows (spin; g_hnew via .cg — intra-kernel)
// =====================================================================
__global__ void __launch_bounds__(64) k2_kernel(
    const float* __restrict__ hidden,
    const float* __restrict__ W_ih,
    const float* __restrict__ b_ih, const float* __restrict__ b_hh,
    const float* __restrict__ stack,
    const float* __restrict__ Wd, const float* __restrict__ bd,
    float* __restrict__ out_o, float* __restrict__ out_h,
    float* __restrict__ out_stack)
{
    int b = blockIdx.x;
    int t = threadIdx.x;

    if (b < 2048) {
        int i = b;
        float pp, po, pn; softmax3_cached(pp, po, pn);
        const float4* s0p = reinterpret_cast<const float4*>(stack);
        const float4* s1p = reinterpret_cast<const float4*>(stack + SW);
        const float4* sip = reinterpret_cast<const float4*>(g_sin);
        float4 v0 = s0p[t], v1 = s1p[t], vs = sip[t];
        float4 st;
        st.x = pn*v0.x + pp*vs.x + po*v1.x;
        st.y = pn*v0.y + pp*vs.y + po*v1.y;
        st.z = pn*v0.z + pp*vs.z + po*v1.z;
        st.w = pn*v0.w + pp*vs.w + po*v1.w;

        const float4* wr = reinterpret_cast<const float4*>(W_ih + (size_t)i * IH + H);
        const float4* wz = reinterpret_cast<const float4*>(W_ih + (size_t)(H + i) * IH + H);
        const float4* wn = reinterpret_cast<const float4*>(W_ih + (size_t)(2 * H + i) * IH + H);
        float ar = dot4(wr[t], st);
        float az = dot4(wz[t], st);
        float an = dot4(wn[t], st);

        __shared__ float sm[2][3];
        int lane = t & 31, wid = t >> 5;
        #pragma unroll
        for (int o = 16; o > 0; o >>= 1) {
            ar += __shfl_down_sync(0xffffffffu, ar, o);
            az += __shfl_down_sync(0xffffffffu, az, o);
            an += __shfl_down_sync(0xffffffffu, an, o);
        }
        if (lane == 0) { sm[wid][0] = ar; sm[wid][1] = az; sm[wid][2] = an; }
        __syncthreads();
        if (t == 0) {
            float AR = sm[0][0] + sm[1][0];
            float AZ = sm[0][1] + sm[1][1];
            float AN = sm[0][2] + sm[1][2];
            float r = 1.0f / (1.0f + expf(-(g_pr[i] + AR + b_ih[i] + b_hh[i])));
            float z = 1.0f / (1.0f + expf(-(g_pz[i] + AZ + b_ih[H + i] + b_hh[H + i])));
            float n = tanhf(g_pgin[i] + AN + b_ih[2 * H + i]
                            + r * (g_pghn[i] + b_hh[2 * H + i]));
            float hn = (1.0f - z) * n + z * hidden[i];
            out_h[i]  = hn;
            g_hnew[i] = hn;
            __threadfence();
            atomicAdd(&g_done, 1);
        }
    } else if (b < 2048 + SD) {
        int d = b - 2048;
        float pp, po, pn; softmax3_cached(pp, po, pn);
        float4 cur = reinterpret_cast<const float4*>(stack + (size_t)d * SW)[t];
        float4 down = make_float4(0.f, 0.f, 0.f, 0.f);
        if (d < SD - 1)
            down = reinterpret_cast<const float4*>(stack + (size_t)(d + 1) * SW)[t];
        float4 up = (d == 0)
            ? reinterpret_cast<const float4*>(g_sin)[t]
            : reinterpret_cast<const float4*>(stack + (size_t)(d - 1) * SW)[t];
        float4 o;
        o.x = pn*cur.x + pp*up.x + po*down.x;
        o.y = pn*cur.y + pp*up.y + po*down.y;
        o.z = pn*cur.z + pp*up.z + po*down.z;
        o.w = pn*cur.w + pp*up.w + po*down.w;
        reinterpret_cast<float4*>(out_stack)[(size_t)d * (SW / 4) + t] = o;
    } else {
        int row = b - (2048 + SD);
        if (t == 0) {
            while (atomicAdd(&g_done, 0) < 2048) __nanosleep(64);
        }
        __syncthreads();

        const float4* w4 = reinterpret_cast<const float4*>(Wd + (size_t)row * H);
        const float4* h4 = reinterpret_cast<const float4*>(g_hnew);
        float s = 0.f;
        #pragma unroll
        for (int u = 0; u < 8; u++) {
            int k = t + u * 64;
            float4 a  = w4[k];
            float4 hv = __ldcg(h4 + k);  // written intra-kernel by other SMs
            s += dot4(a, hv);
        }
        __shared__ float sm2[2];
        int lane = t & 31, wid = t >> 5;
        #pragma unroll
        for (int o = 16; o > 0; o >>= 1) s += __shfl_down_sync(0xffffffffu, s, o);
        if (lane == 0) sm2[wid] = s;
        __syncthreads();
        if (t == 0) out_o[row] = sm2[0] + sm2[1] + bd[row];
    }
}

extern "C" void kernel_launch(void* const* d_in, const int* in_sizes, int n_in,
                              void* d_out, int out_size) {
    const int*   inp    = (const int*)  d_in[0];
    const float* hidden = (const float*)d_in[1];
    const float* stack  = (const float*)d_in[2];
    const float* emb    = (const float*)d_in[3];
    const float* Wc     = (const float*)d_in[4];
    const float* bc     = (const float*)d_in[5];
    const float* Ws     = (const float*)d_in[6];
    const float* bs     = (const float*)d_in[7];
    const float* W_ih   = (const float*)d_in[8];
    const float* b_ih   = (const float*)d_in[9];
    const float* W_hh   = (const float*)d_in[10];
    const float* b_hh   = (const float*)d_in[11];
    const float* Wd     = (const float*)d_in[12];
    const float* bd     = (const float*)d_in[13];

    float* out       = (float*)d_out;
    float* out_o     = out;            // (1,O)     : 128
    float* out_h     = out + O;        // (1,1,H)   : 2048
    float* out_stack = out + O + H;    // (1,SD,SW) : 51200

    k1_kernel<<<2048 + 3 + SW, 256>>>(hidden, inp, emb, W_ih, W_hh,
                                      Wc, bc, Ws, bs);
    k2_kernel<<<2048 + SD + O, 64>>>(hidden, W_ih, b_ih, b_hh, stack,
                                     Wd, bd, out_o, out_h, out_stack);
}